// round 7
// baseline (speedup 1.0000x reference)
#include <cuda_runtime.h>
#include <math_constants.h>

#define NCLS 81          // num_classes + 1
#define NBASE 60
#define NEG_LBL 80
#define MIN_SAMP 2
#define TROWS 128        // rows per block == threads per block

// Zero-initialized at module load; the last block of each launch resets them,
// so every kernel_launch call / graph replay starts from clean state.
__device__ double   g_lsum[NCLS];
__device__ int      g_lcnt[NCLS];
__device__ unsigned g_done;

__global__ void __launch_bounds__(TROWS) adl_fused_kernel(
    const float* __restrict__ score,
    const int*   __restrict__ labels,
    const float* __restrict__ lw,
    float* __restrict__ out,
    int n, int out_size)
{
    __shared__ __align__(16) float tile[TROWS * NCLS];  // 41472 B
    __shared__ float lsum[NCLS];
    __shared__ int   lcnt[NCLS];
    __shared__ int   is_last;

    const int tid = threadIdx.x;

    if (tid < NCLS) { lsum[tid] = 0.f; lcnt[tid] = 0; }

    const int row0  = blockIdx.x * TROWS;
    const int nrows = min(TROWS, n - row0);

    // Stage tile: 128 rows * 81 floats contiguous = 2592 float4.
    // Global byte offset = blockIdx * 41472 -> 16B aligned.
    if (nrows == TROWS) {
        const float4* __restrict__ src =
            (const float4*)(score + (size_t)row0 * NCLS);
        float4* dst = (float4*)tile;
        #pragma unroll
        for (int i = 0; i < 20; i++)
            dst[tid + i * TROWS] = src[tid + i * TROWS];
        if (tid < 32)                        // remainder: 2592 - 2560
            dst[tid + 20 * TROWS] = src[tid + 20 * TROWS];
    } else {
        const float* src = score + (size_t)row0 * NCLS;
        const int nfl = nrows * NCLS;
        for (int i = tid; i < nfl; i += TROWS) tile[i] = src[i];
    }
    __syncthreads();

    if (tid < nrows) {
        const int row = row0 + tid;
        float* r = tile + tid * NCLS;   // word stride 81 (odd): conflict-free

        // Pass 1: e = exp(s) (scores are O(1); softmax shift-invariant, skip
        // the max pass), Z = sum e, store e back in place.
        float z = 0.f;
        #pragma unroll 9
        for (int k = 0; k < NCLS; k++) {
            float e = __expf(r[k]);
            r[k] = e;
            z += e;
        }
        const float invZ = __fdividef(1.f, z);

        const int   lbl  = labels[row];
        const float wrow = lw[row];
        const float pt   = r[lbl] * invZ;

        // Pass 2: sum_c min(-log(clamp(pt - p_c, 1e-3, 1)), 5).
        // True-class column contributes exactly min(-log(1e-3),5)=5; subtract.
        float t = 0.f;
        #pragma unroll 9
        for (int k = 0; k < NCLS; k++) {
            float d = fminf(fmaxf(pt - r[k] * invZ, 1e-3f), 1.f);
            t += fminf(-__logf(d), 5.f);
        }

        float om = fminf(fmaxf(1.f - pt, 1e-4f), 1.f);
        float row_sum = om * om * (t - 5.f);

        if (wrow > 0.f) {                    // per-LABEL accumulation
            atomicAdd(&lsum[lbl], row_sum);
            atomicAdd(&lcnt[lbl], 1);
        }
    }
    __syncthreads();

    // Flush block bins to global (81 spread L2 addresses).
    if (tid < NCLS && lcnt[tid] > 0) {
        atomicAdd(&g_lsum[tid], (double)lsum[tid]);
        atomicAdd(&g_lcnt[tid], lcnt[tid]);
    }

    // Last-block ticket.
    __threadfence();
    if (tid == 0)
        is_last = (atomicAdd(&g_done, 1u) == gridDim.x - 1);
    __syncthreads();
    if (!is_last) return;
    __threadfence();

    // ---- Finalization (single block) ----
    __shared__ double fsum[NCLS];
    __shared__ int    fcnt[NCLS];
    if (tid < NCLS) {
        fsum[tid] = *(volatile double*)&g_lsum[tid];
        fcnt[tid] = *(volatile int*)&g_lcnt[tid];
    }
    __syncthreads();

    if (tid == 0) {
        double s[3] = {0.0, 0.0, 0.0};
        long long c[3] = {0, 0, 0};
        for (int l = 0; l < NEG_LBL; l++) {
            if (fcnt[l] >= MIN_SAMP) {
                int g = (l < NBASE) ? 0 : 1;
                s[g] += fsum[l];
                c[g] += fcnt[l];
            }
        }
        s[2] = fsum[NEG_LBL];               // neg: no min-sample filter
        c[2] = fcnt[NEG_LBL];

        const double W[3] = {1.0 / 30.0, 0.1, 0.001};  // base, novel, neg
        for (int g = 0; g < 3; g++) {
            long long nn = c[g];
            double denom = (double)(nn > 0 ? nn : 1) * (double)(NCLS - 1);
            double mean = (nn > 0) ? (s[g] / denom) : 0.0;
            double loss = fmin(mean * W[g], 1.0);
            if (g < out_size) out[g] = (float)loss;
        }
    }

    // Reset globals for the next launch / graph replay.
    if (tid < NCLS) { g_lsum[tid] = 0.0; g_lcnt[tid] = 0; }
    if (tid == 0) g_done = 0u;
}

extern "C" void kernel_launch(void* const* d_in, const int* in_sizes, int n_in,
                              void* d_out, int out_size) {
    const float* score  = (const float*)d_in[0];
    const int*   labels = (const int*)d_in[1];
    const float* lw     = (const float*)d_in[2];
    float* out = (float*)d_out;
    const int n = in_sizes[1];   // N rows (labels element count)

    adl_fused_kernel<<<(n + TROWS - 1) / TROWS, TROWS>>>(
        score, labels, lw, out, n, out_size);
}